// round 1
// baseline (speedup 1.0000x reference)
#include <cuda_runtime.h>

#define NB   32
#define CC   256
#define HH   56
#define WW   56
#define HW   (HH*WW)        // 3136
#define NHW  (NB*HW)        // 100352
#define COUT 256
#define KK   9
#define CIN_K (CC*KK)       // 2304

#define TILE 16
#define CI_CHUNK 8
#define CO_BLK 64

// ---- scratch (no allocations allowed; __device__ globals) ----
__device__ float g_scale[CC];
__device__ float g_shift[CC];
__device__ float g_xb[(size_t)NB*CC*HW];   // sign(xn), +-1 (or 0) as fp32
__device__ float g_m[NHW];                 // channel-mean of |xn|
__device__ float g_betamap[NHW];           // 3x3 box filter of g_m
__device__ float g_wb[(size_t)COUT*CIN_K]; // sign(W)
__device__ float g_alpha[COUT];

// K1: per-channel batch stats -> affine (scale, shift) so xn = x*scale + shift
__global__ void stats_kernel(const float* __restrict__ x,
                             const float* __restrict__ gamma,
                             const float* __restrict__ beta_bn) {
    int c = blockIdx.x;
    int tid = threadIdx.x;
    float s = 0.f, s2 = 0.f;
    for (int n = 0; n < NB; n++) {
        const float* p = x + ((size_t)n*CC + c)*HW;
        for (int i = tid; i < HW; i += blockDim.x) {
            float v = p[i];
            s += v; s2 += v*v;
        }
    }
    __shared__ float sh[256], sh2[256];
    sh[tid] = s; sh2[tid] = s2;
    __syncthreads();
    for (int off = 128; off > 0; off >>= 1) {
        if (tid < off) { sh[tid] += sh[tid+off]; sh2[tid] += sh2[tid+off]; }
        __syncthreads();
    }
    if (tid == 0) {
        float mu  = sh[0]  * (1.0f/(float)NHW);
        float var = sh2[0] * (1.0f/(float)NHW) - mu*mu;
        float inv = rsqrtf(var + 1e-4f);
        float sc  = gamma[c]*inv;
        g_scale[c] = sc;
        g_shift[c] = beta_bn[c] - mu*sc;
    }
}

// K2: binarize activations + per-pixel channel-mean of |xn|
__global__ void binact_kernel(const float* __restrict__ x) {
    int gp = blockIdx.x*blockDim.x + threadIdx.x;
    if (gp >= NHW) return;
    int n = gp / HW;
    int p = gp % HW;
    const float* xp = x    + (size_t)n*CC*HW + p;
    float*      xbp = g_xb + (size_t)n*CC*HW + p;
    float acc = 0.f;
    for (int c = 0; c < CC; c++) {
        float v = xp[(size_t)c*HW] * g_scale[c] + g_shift[c];
        acc += fabsf(v);
        xbp[(size_t)c*HW] = (v > 0.f) ? 1.f : ((v < 0.f) ? -1.f : 0.f);
    }
    g_m[gp] = acc * (1.0f/(float)CC);
}

// K3: 3x3 box filter (zero pad) on g_m -> g_betamap
__global__ void box_kernel() {
    int gp = blockIdx.x*blockDim.x + threadIdx.x;
    if (gp >= NHW) return;
    int n = gp / HW;
    int p = gp % HW;
    int h = p / WW, w = p % WW;
    const float* mp = g_m + (size_t)n*HW;
    float s = 0.f;
    #pragma unroll
    for (int dh = -1; dh <= 1; dh++)
        #pragma unroll
        for (int dw = -1; dw <= 1; dw++) {
            int hh = h + dh, ww2 = w + dw;
            if (hh >= 0 && hh < HH && ww2 >= 0 && ww2 < WW)
                s += mp[hh*WW + ww2];
        }
    g_betamap[gp] = s * (1.0f/9.0f);
}

// K4: binarize weights + alpha = mean(|W|) per output filter
__global__ void wprep_kernel(const float* __restrict__ Wt) {
    int co = blockIdx.x;
    int tid = threadIdx.x;
    const float* wp  = Wt   + (size_t)co*CIN_K;
    float*       wbp = g_wb + (size_t)co*CIN_K;
    float s = 0.f;
    for (int i = tid; i < CIN_K; i += blockDim.x) {
        float v = wp[i];
        s += fabsf(v);
        wbp[i] = (v > 0.f) ? 1.f : ((v < 0.f) ? -1.f : 0.f);
    }
    __shared__ float sh[256];
    sh[tid] = s;
    __syncthreads();
    for (int off = 128; off > 0; off >>= 1) {
        if (tid < off) sh[tid] += sh[tid+off];
        __syncthreads();
    }
    if (tid == 0) g_alpha[co] = sh[0] * (1.0f/(float)CIN_K);
}

// K5: tiled direct conv (binarized inputs/weights, exact in fp32) + epilogue
__global__ __launch_bounds__(256) void conv_kernel(const float* __restrict__ bias,
                                                   float* __restrict__ out) {
    __shared__ float s_in[CI_CHUNK][TILE+2][TILE+2];
    __shared__ float s_w[CO_BLK][CI_CHUNK][KK];

    int tid  = threadIdx.y*TILE + threadIdx.x;
    int tile = blockIdx.x;                 // 0..15 (4x4 tiles of 16 covering 56x56)
    int th0  = (tile >> 2) * TILE;
    int tw0  = (tile & 3) * TILE;
    int cob  = blockIdx.y * CO_BLK;
    int n    = blockIdx.z;

    float acc[CO_BLK];
    #pragma unroll
    for (int i = 0; i < CO_BLK; i++) acc[i] = 0.f;

    const float* xb_n = g_xb + (size_t)n*CC*HW;

    for (int cic = 0; cic < CC; cic += CI_CHUNK) {
        // load input tile (with halo, zero-padded)
        for (int i = tid; i < CI_CHUNK*(TILE+2)*(TILE+2); i += 256) {
            int ci = i / ((TILE+2)*(TILE+2));
            int r  = (i / (TILE+2)) % (TILE+2);
            int cc = i % (TILE+2);
            int gh = th0 + r - 1;
            int gw = tw0 + cc - 1;
            float v = 0.f;
            if (gh >= 0 && gh < HH && gw >= 0 && gw < WW)
                v = xb_n[(size_t)(cic+ci)*HW + gh*WW + gw];
            s_in[ci][r][cc] = v;
        }
        // load weight block
        for (int i = tid; i < CO_BLK*CI_CHUNK*KK; i += 256) {
            int co  = i / (CI_CHUNK*KK);
            int rem = i % (CI_CHUNK*KK);
            int ci  = rem / KK;
            int t   = rem % KK;
            s_w[co][ci][t] = g_wb[(size_t)(cob+co)*CIN_K + (size_t)(cic+ci)*KK + t];
        }
        __syncthreads();

        #pragma unroll 1
        for (int ci = 0; ci < CI_CHUNK; ci++) {
            float v[KK];
            #pragma unroll
            for (int t = 0; t < KK; t++)
                v[t] = s_in[ci][threadIdx.y + t/3][threadIdx.x + t%3];
            #pragma unroll
            for (int co = 0; co < CO_BLK; co++) {
                #pragma unroll
                for (int t = 0; t < KK; t++)
                    acc[co] += v[t] * s_w[co][ci][t];
            }
        }
        __syncthreads();
    }

    int oh = th0 + threadIdx.y;
    int ow = tw0 + threadIdx.x;
    if (oh < HH && ow < WW) {
        float bm = g_betamap[(size_t)n*HW + oh*WW + ow];
        #pragma unroll
        for (int co = 0; co < CO_BLK; co++) {
            float yv = (acc[co] + bias[cob+co]) * bm * g_alpha[cob+co];
            out[((size_t)n*COUT + cob + co)*HW + oh*WW + ow] = fmaxf(yv, 0.f);
        }
    }
}

extern "C" void kernel_launch(void* const* d_in, const int* in_sizes, int n_in,
                              void* d_out, int out_size) {
    const float* x       = (const float*)d_in[0];
    const float* gamma   = (const float*)d_in[1];
    const float* beta_bn = (const float*)d_in[2];
    const float* Wt      = (const float*)d_in[3];
    const float* b       = (const float*)d_in[4];
    float* out = (float*)d_out;

    stats_kernel<<<CC, 256>>>(x, gamma, beta_bn);
    binact_kernel<<<(NHW + 255)/256, 256>>>(x);
    box_kernel<<<(NHW + 255)/256, 256>>>();
    wprep_kernel<<<COUT, 256>>>(Wt);
    conv_kernel<<<dim3(16, COUT/CO_BLK, NB), dim3(TILE, TILE)>>>(b, out);
}

// round 3
// speedup vs baseline: 8.4743x; 8.4743x over previous
#include <cuda_runtime.h>
#include <cstdint>

#define NB   32
#define CC   256
#define HH   56
#define WW   56
#define HW   3136
#define NHW  100352
#define COUT 256
#define KK   9
#define CIN_K 2304
#define PADW 58
#define XBP_PIX 3584   // >= 3455 + 118 max tap offset, padded region stays zero

// ---------------- scratch (device globals; zero-init => padding stays 0) -------
__device__ float g_scale[CC];
__device__ float g_shift[CC];
__device__ float g_m[NHW];
__device__ float g_betamap[NHW];
__device__ float g_alpha[COUT];
__device__ int8_t g_xb8[(size_t)NB * XBP_PIX * CC];   // [n][padded pix][c]  (+-1/0)
__device__ int8_t g_wb8[(size_t)COUT * CIN_K];        // [cout][tap*256+ci]  (+-1/0)

// ---------------- helpers ----------------
__device__ __forceinline__ uint32_t smem_u32(const void* p) {
    uint32_t a;
    asm("{ .reg .u64 t; cvta.to.shared.u64 t, %1; cvt.u32.u64 %0, t; }" : "=r"(a) : "l"(p));
    return a;
}
#define SWZ(o) ((o) ^ (((o) >> 3) & 0x70))
__device__ __forceinline__ void cp16(uint32_t dst, const void* src) {
    asm volatile("cp.async.cg.shared.global [%0], [%1], 16;" :: "r"(dst), "l"(src));
}
__device__ __forceinline__ void ldsm4(uint32_t* r, uint32_t addr) {
    asm volatile("ldmatrix.sync.aligned.m8n8.x4.shared.b16 {%0,%1,%2,%3}, [%4];"
                 : "=r"(r[0]), "=r"(r[1]), "=r"(r[2]), "=r"(r[3]) : "r"(addr));
}
__device__ __forceinline__ void mma_s8(int* d, const uint32_t* a, uint32_t b0, uint32_t b1) {
    asm volatile("mma.sync.aligned.m16n8k32.row.col.s32.s8.s8.s32 "
                 "{%0,%1,%2,%3}, {%4,%5,%6,%7}, {%8,%9}, {%0,%1,%2,%3};"
                 : "+r"(d[0]), "+r"(d[1]), "+r"(d[2]), "+r"(d[3])
                 : "r"(a[0]), "r"(a[1]), "r"(a[2]), "r"(a[3]), "r"(b0), "r"(b1));
}

// ---------------- K1: BN batch stats -> affine ----------------
__global__ void stats_kernel(const float* __restrict__ x,
                             const float* __restrict__ gamma,
                             const float* __restrict__ beta_bn) {
    int c = blockIdx.x, tid = threadIdx.x;
    float s = 0.f, s2 = 0.f;
    for (int n = 0; n < NB; n++) {
        const float* p = x + ((size_t)n * CC + c) * HW;
        for (int i = tid; i < HW; i += blockDim.x) { float v = p[i]; s += v; s2 += v * v; }
    }
    __shared__ float sh[256], sh2[256];
    sh[tid] = s; sh2[tid] = s2; __syncthreads();
    for (int off = 128; off > 0; off >>= 1) {
        if (tid < off) { sh[tid] += sh[tid + off]; sh2[tid] += sh2[tid + off]; }
        __syncthreads();
    }
    if (tid == 0) {
        float mu  = sh[0] * (1.0f / (float)NHW);
        float var = sh2[0] * (1.0f / (float)NHW) - mu * mu;
        float inv = rsqrtf(var + 1e-4f);
        float sc  = gamma[c] * inv;
        g_scale[c] = sc;
        g_shift[c] = beta_bn[c] - mu * sc;
    }
}

// ---------------- K2: binarize+pack s8 channels-last padded, + |xn| mean -------
__global__ void binact_pack_kernel(const float* __restrict__ x) {
    int gp = blockIdx.x * blockDim.x + threadIdx.x;
    if (gp >= NHW) return;
    int n = gp / HW, p = gp % HW;
    int h = p / WW, w = p % WW;
    const float* xp = x + (size_t)n * CC * HW + p;
    int8_t* dst = g_xb8 + ((size_t)n * XBP_PIX + (h + 1) * PADW + (w + 1)) * CC;
    float acc = 0.f;
    for (int c0 = 0; c0 < CC; c0 += 16) {
        int8_t buf[16];
        #pragma unroll
        for (int cc = 0; cc < 16; cc++) {
            int c = c0 + cc;
            float v = xp[(size_t)c * HW] * g_scale[c] + g_shift[c];
            acc += fabsf(v);
            buf[cc] = (v > 0.f) ? (int8_t)1 : ((v < 0.f) ? (int8_t)-1 : (int8_t)0);
        }
        *reinterpret_cast<uint4*>(dst + c0) = *reinterpret_cast<uint4*>(buf);
    }
    g_m[gp] = acc * (1.0f / (float)CC);
}

// ---------------- K3: 3x3 box filter ----------------
__global__ void box_kernel() {
    int gp = blockIdx.x * blockDim.x + threadIdx.x;
    if (gp >= NHW) return;
    int n = gp / HW, p = gp % HW;
    int h = p / WW, w = p % WW;
    const float* mp = g_m + (size_t)n * HW;
    float s = 0.f;
    #pragma unroll
    for (int dh = -1; dh <= 1; dh++)
        #pragma unroll
        for (int dw = -1; dw <= 1; dw++) {
            int hh = h + dh, ww2 = w + dw;
            if (hh >= 0 && hh < HH && ww2 >= 0 && ww2 < WW) s += mp[hh * WW + ww2];
        }
    g_betamap[gp] = s * (1.0f / 9.0f);
}

// ---------------- K4: weight binarize + tap-major reorder + alpha --------------
__global__ void wprep_kernel(const float* __restrict__ Wt) {
    int co = blockIdx.x, tid = threadIdx.x;
    const float* wp = Wt + (size_t)co * CIN_K;
    int8_t* wbp = g_wb8 + (size_t)co * CIN_K;
    float s = 0.f;
    for (int i = tid; i < CIN_K; i += blockDim.x) {
        float v = wp[i];
        s += fabsf(v);
        int ci = i / KK, tap = i % KK;
        wbp[tap * CC + ci] = (v > 0.f) ? (int8_t)1 : ((v < 0.f) ? (int8_t)-1 : (int8_t)0);
    }
    __shared__ float sh[256];
    sh[tid] = s; __syncthreads();
    for (int off = 128; off > 0; off >>= 1) {
        if (tid < off) sh[tid] += sh[tid + off];
        __syncthreads();
    }
    if (tid == 0) g_alpha[co] = sh[0] * (1.0f / (float)CIN_K);
}

// ---------------- K5: IMMA implicit-GEMM conv + fused epilogue -----------------
// CTA: 128 pixels (M) x 128 couts (N); K = 18 chunks of 128 (tap x 128ci-half)
// smem: stage = A(128x128 s8, 16KB) + B(128x128 s8, 16KB) = 32KB, double buffered
#define STAGE 32768
#define OFF_B 16384
#define NCHUNK 18

__device__ __forceinline__ void load_stage(uint32_t sm, int n, int b0, int cob,
                                           int chunk, int tid) {
    int t = chunk >> 1;                 // tap 0..8
    int q = chunk & 1;                  // 128-ci half
    int off_t = (t / 3) * PADW + (t % 3);
    uint32_t sbase = sm + (chunk & 1 ? STAGE : 0);
    const int8_t* a0 = g_xb8 + ((size_t)n * XBP_PIX + b0 + off_t) * CC + q * 128;
    const int8_t* bs = g_wb8 + (size_t)cob * CIN_K + t * CC + q * 128;
    #pragma unroll
    for (int i = 0; i < 4; i++) {       // A: 128 rows x 128B
        int slot = tid + 256 * i; int row = slot >> 3, c16 = slot & 7;
        cp16(sbase + SWZ(row * 128 + c16 * 16), a0 + (size_t)row * CC + c16 * 16);
    }
    #pragma unroll
    for (int i = 0; i < 4; i++) {       // B: 128 couts x 128B
        int slot = tid + 256 * i; int row = slot >> 3, c16 = slot & 7;
        cp16(sbase + OFF_B + SWZ(row * 128 + c16 * 16), bs + (size_t)row * CIN_K + c16 * 16);
    }
    asm volatile("cp.async.commit_group;" ::: "memory");
}

__global__ void __launch_bounds__(256, 2)
conv_mma_kernel(const float* __restrict__ bias, float* __restrict__ out) {
    extern __shared__ __align__(1024) char smem[];
    uint32_t sm = smem_u32(smem);
    int tid = threadIdx.x, wid = tid >> 5, lane = tid & 31;
    int b0  = blockIdx.x * 128;
    int cob = blockIdx.y * 128;
    int n   = blockIdx.z;
    int wm = wid & 3, wn = wid >> 2;    // warp tile: 32 pixels x 64 couts

    // ldmatrix lane decode: tile = lane/8 -> {row+8?, byte16?}
    int lrow = (lane & 7) + ((lane >> 3) & 1) * 8;
    uint32_t ltb = (uint32_t)((lane >> 4) * 16);
    uint32_t xk  = (uint32_t)((lane & 7) << 4);

    uint32_t aA[2], aB[4];
    #pragma unroll
    for (int mi = 0; mi < 2; mi++) aA[mi] = (uint32_t)((wm * 32 + mi * 16 + lrow) * 128);
    #pragma unroll
    for (int nj = 0; nj < 4; nj++) aB[nj] = (uint32_t)(OFF_B + (wn * 64 + nj * 16 + lrow) * 128);

    int acc[2][8][4];
    #pragma unroll
    for (int mi = 0; mi < 2; mi++)
        #pragma unroll
        for (int ni = 0; ni < 8; ni++)
            #pragma unroll
            for (int j = 0; j < 4; j++) acc[mi][ni][j] = 0;

    load_stage(sm, n, b0, cob, 0, tid);

    for (int k = 0; k < NCHUNK; k++) {
        if (k + 1 < NCHUNK) {
            load_stage(sm, n, b0, cob, k + 1, tid);
            asm volatile("cp.async.wait_group 1;" ::: "memory");
        } else {
            asm volatile("cp.async.wait_group 0;" ::: "memory");
        }
        __syncthreads();
        uint32_t sb = sm + ((k & 1) ? STAGE : 0);
        #pragma unroll
        for (int ks = 0; ks < 4; ks++) {
            uint32_t off = (((uint32_t)(ks << 5)) | ltb) ^ xk;
            uint32_t a[2][4], bf[4][4];
            ldsm4(a[0], sb + aA[0] + off);
            ldsm4(a[1], sb + aA[1] + off);
            #pragma unroll
            for (int nj = 0; nj < 4; nj++) ldsm4(bf[nj], sb + aB[nj] + off);
            #pragma unroll
            for (int mi = 0; mi < 2; mi++)
                #pragma unroll
                for (int ni = 0; ni < 8; ni++) {
                    int nj = ni >> 1, sel = ni & 1;
                    mma_s8(acc[mi][ni], a[mi], bf[nj][sel], bf[nj][sel + 2]);
                }
        }
        __syncthreads();
    }

    // epilogue: c-layout: reg j: row += (j>>1)*8, col += (j&1)
    #pragma unroll
    for (int mi = 0; mi < 2; mi++) {
        #pragma unroll
        for (int half = 0; half < 2; half++) {
            int b = b0 + wm * 32 + mi * 16 + (lane >> 2) + half * 8;
            int h = b / PADW, wp = b % PADW;
            bool valid = (h < HH) && (wp < WW);
            float bm = valid ? g_betamap[(size_t)n * HW + h * WW + wp] : 0.f;
            float* obase = out + (size_t)n * COUT * HW + h * WW + wp;
            if (valid) {
                #pragma unroll
                for (int ni = 0; ni < 8; ni++) {
                    #pragma unroll
                    for (int j2 = 0; j2 < 2; j2++) {
                        int co = cob + wn * 64 + ni * 8 + 2 * (lane & 3) + j2;
                        float v = ((float)acc[mi][ni][half * 2 + j2] + bias[co])
                                  * bm * g_alpha[co];
                        obase[(size_t)co * HW] = fmaxf(v, 0.f);
                    }
                }
            }
        }
    }
}

// ---------------- launcher ----------------
extern "C" void kernel_launch(void* const* d_in, const int* in_sizes, int n_in,
                              void* d_out, int out_size) {
    const float* x       = (const float*)d_in[0];
    const float* gamma   = (const float*)d_in[1];
    const float* beta_bn = (const float*)d_in[2];
    const float* Wt      = (const float*)d_in[3];
    const float* b       = (const float*)d_in[4];
    float* out = (float*)d_out;

    cudaFuncSetAttribute(conv_mma_kernel,
                         cudaFuncAttributeMaxDynamicSharedMemorySize, 2 * STAGE);

    stats_kernel<<<CC, 256>>>(x, gamma, beta_bn);
    binact_pack_kernel<<<(NHW + 255) / 256, 256>>>(x);
    box_kernel<<<(NHW + 255) / 256, 256>>>();
    wprep_kernel<<<COUT, 256>>>(Wt);
    conv_mma_kernel<<<dim3(27, 2, NB), 256, 2 * STAGE>>>(b, out);
}

// round 4
// speedup vs baseline: 8.5548x; 1.0095x over previous
#include <cuda_runtime.h>
#include <cstdint>

#define NB   32
#define CC   256
#define HH   56
#define WW   56
#define HW   3136
#define NHW  100352
#define COUT 256
#define KK   9
#define CIN_K 2304
#define PADW 58
#define XBP_PIX 3584

// ---------------- scratch (device globals; zero-init => padding stays 0) -------
__device__ float g_scale[CC];
__device__ float g_shift[CC];
__device__ float g_m[NHW];
__device__ float g_betamap[NHW];
__device__ float g_alpha[COUT];
__device__ int8_t g_xb8[(size_t)NB * XBP_PIX * CC];
__device__ int8_t g_wb8[(size_t)COUT * CIN_K];

// ---------------- helpers ----------------
__device__ __forceinline__ uint32_t smem_u32(const void* p) {
    uint32_t a;
    asm("{ .reg .u64 t; cvta.to.shared.u64 t, %1; cvt.u32.u64 %0, t; }" : "=r"(a) : "l"(p));
    return a;
}
#define SWZ(o) ((o) ^ (((o) >> 3) & 0x70))
__device__ __forceinline__ void cp16(uint32_t dst, const void* src) {
    asm volatile("cp.async.cg.shared.global [%0], [%1], 16;" :: "r"(dst), "l"(src));
}
__device__ __forceinline__ void ldsm4(uint32_t* r, uint32_t addr) {
    asm volatile("ldmatrix.sync.aligned.m8n8.x4.shared.b16 {%0,%1,%2,%3}, [%4];"
                 : "=r"(r[0]), "=r"(r[1]), "=r"(r[2]), "=r"(r[3]) : "r"(addr));
}
__device__ __forceinline__ void mma_s8(int* d, const uint32_t* a, uint32_t b0, uint32_t b1) {
    asm volatile("mma.sync.aligned.m16n8k32.row.col.s32.s8.s8.s32 "
                 "{%0,%1,%2,%3}, {%4,%5,%6,%7}, {%8,%9}, {%0,%1,%2,%3};"
                 : "+r"(d[0]), "+r"(d[1]), "+r"(d[2]), "+r"(d[3])
                 : "r"(a[0]), "r"(a[1]), "r"(a[2]), "r"(a[3]), "r"(b0), "r"(b1));
}

// ---------------- K1: BN batch stats -> affine ----------------
__global__ void stats_kernel(const float* __restrict__ x,
                             const float* __restrict__ gamma,
                             const float* __restrict__ beta_bn) {
    int c = blockIdx.x, tid = threadIdx.x;
    float s = 0.f, s2 = 0.f;
    for (int n = 0; n < NB; n++) {
        const float* p = x + ((size_t)n * CC + c) * HW;
        for (int i = tid; i < HW; i += blockDim.x) { float v = p[i]; s += v; s2 += v * v; }
    }
    __shared__ float sh[256], sh2[256];
    sh[tid] = s; sh2[tid] = s2; __syncthreads();
    for (int off = 128; off > 0; off >>= 1) {
        if (tid < off) { sh[tid] += sh[tid + off]; sh2[tid] += sh2[tid + off]; }
        __syncthreads();
    }
    if (tid == 0) {
        float mu  = sh[0] * (1.0f / (float)NHW);
        float var = sh2[0] * (1.0f / (float)NHW) - mu * mu;
        float inv = rsqrtf(var + 1e-4f);
        float sc  = gamma[c] * inv;
        g_scale[c] = sc;
        g_shift[c] = beta_bn[c] - mu * sc;
    }
}

// ---------------- K2: binarize+pack s8 channels-last padded, + |xn| mean -------
__global__ void binact_pack_kernel(const float* __restrict__ x) {
    int gp = blockIdx.x * blockDim.x + threadIdx.x;
    if (gp >= NHW) return;
    int n = gp / HW, p = gp % HW;
    int h = p / WW, w = p % WW;
    const float* xp = x + (size_t)n * CC * HW + p;
    int8_t* dst = g_xb8 + ((size_t)n * XBP_PIX + (h + 1) * PADW + (w + 1)) * CC;
    float acc = 0.f;
    for (int c0 = 0; c0 < CC; c0 += 16) {
        int8_t buf[16];
        #pragma unroll
        for (int cc = 0; cc < 16; cc++) {
            int c = c0 + cc;
            float v = xp[(size_t)c * HW] * g_scale[c] + g_shift[c];
            acc += fabsf(v);
            buf[cc] = (v > 0.f) ? (int8_t)1 : ((v < 0.f) ? (int8_t)-1 : (int8_t)0);
        }
        *reinterpret_cast<uint4*>(dst + c0) = *reinterpret_cast<uint4*>(buf);
    }
    g_m[gp] = acc * (1.0f / (float)CC);
}

// ---------------- K3: merged box filter + weight prep (keeps conv at launch #3) ----
#define BOX_BLOCKS ((NHW + 255) / 256)
__global__ void boxwprep_kernel(const float* __restrict__ Wt) {
    if (blockIdx.x < BOX_BLOCKS) {
        int gp = blockIdx.x * blockDim.x + threadIdx.x;
        if (gp >= NHW) return;
        int n = gp / HW, p = gp % HW;
        int h = p / WW, w = p % WW;
        const float* mp = g_m + (size_t)n * HW;
        float s = 0.f;
        #pragma unroll
        for (int dh = -1; dh <= 1; dh++)
            #pragma unroll
            for (int dw = -1; dw <= 1; dw++) {
                int hh = h + dh, ww2 = w + dw;
                if (hh >= 0 && hh < HH && ww2 >= 0 && ww2 < WW) s += mp[hh * WW + ww2];
            }
        g_betamap[gp] = s * (1.0f / 9.0f);
    } else {
        int co = blockIdx.x - BOX_BLOCKS, tid = threadIdx.x;
        const float* wp = Wt + (size_t)co * CIN_K;
        int8_t* wbp = g_wb8 + (size_t)co * CIN_K;
        float s = 0.f;
        for (int i = tid; i < CIN_K; i += blockDim.x) {
            float v = wp[i];
            s += fabsf(v);
            int ci = i / KK, tap = i % KK;
            wbp[tap * CC + ci] = (v > 0.f) ? (int8_t)1 : ((v < 0.f) ? (int8_t)-1 : (int8_t)0);
        }
        __shared__ float sh[256];
        sh[tid] = s; __syncthreads();
        for (int off = 128; off > 0; off >>= 1) {
            if (tid < off) sh[tid] += sh[tid + off];
            __syncthreads();
        }
        if (tid == 0) g_alpha[co] = sh[0] * (1.0f / (float)CIN_K);
    }
}

// ---------------- K4: IMMA implicit-GEMM conv, 3-stage pipeline ----------------
#define STAGE 32768
#define OFF_B 16384
#define NCHUNK 18
#define NSTAGE 3

__device__ __forceinline__ void load_stage(uint32_t sbase, const int8_t* aBase,
                                           const int8_t* bBase, int chunk, int tid) {
    int t = chunk >> 1;                 // tap 0..8
    int q = chunk & 1;                  // 128-ci half
    int off_t = (t / 3) * PADW + (t % 3);
    const int8_t* a0 = aBase + (size_t)off_t * CC + q * 128;
    const int8_t* bs = bBase + t * CC + q * 128;
    #pragma unroll
    for (int i = 0; i < 4; i++) {       // A: 128 rows x 128B
        int slot = tid + 256 * i; int row = slot >> 3, c16 = slot & 7;
        cp16(sbase + SWZ(row * 128 + c16 * 16), a0 + (size_t)row * CC + c16 * 16);
    }
    #pragma unroll
    for (int i = 0; i < 4; i++) {       // B: 128 couts x 128B
        int slot = tid + 256 * i; int row = slot >> 3, c16 = slot & 7;
        cp16(sbase + OFF_B + SWZ(row * 128 + c16 * 16), bs + (size_t)row * CIN_K + c16 * 16);
    }
    asm volatile("cp.async.commit_group;" ::: "memory");
}

__global__ void __launch_bounds__(256, 2)
conv_mma_kernel(const float* __restrict__ bias, float* __restrict__ out) {
    extern __shared__ __align__(1024) char smem[];
    uint32_t sm = smem_u32(smem);
    int tid = threadIdx.x, wid = tid >> 5, lane = tid & 31;
    int b0  = blockIdx.x * 128;
    int cob = blockIdx.y * 128;
    int n   = blockIdx.z;
    int wm = wid & 3, wn = wid >> 2;    // warp tile: 32 pixels x 64 couts

    const int8_t* aBase = g_xb8 + ((size_t)n * XBP_PIX + b0) * CC;
    const int8_t* bBase = g_wb8 + (size_t)cob * CIN_K;

    int lrow = (lane & 7) + ((lane >> 3) & 1) * 8;
    uint32_t ltb = (uint32_t)((lane >> 4) * 16);
    uint32_t xk  = (uint32_t)((lane & 7) << 4);

    uint32_t aA[2], aB[4];
    #pragma unroll
    for (int mi = 0; mi < 2; mi++) aA[mi] = (uint32_t)((wm * 32 + mi * 16 + lrow) * 128);
    #pragma unroll
    for (int nj = 0; nj < 4; nj++) aB[nj] = (uint32_t)(OFF_B + (wn * 64 + nj * 16 + lrow) * 128);

    int acc[2][8][4];
    #pragma unroll
    for (int mi = 0; mi < 2; mi++)
        #pragma unroll
        for (int ni = 0; ni < 8; ni++)
            #pragma unroll
            for (int j = 0; j < 4; j++) acc[mi][ni][j] = 0;

    load_stage(sm + 0 * STAGE, aBase, bBase, 0, tid);
    load_stage(sm + 1 * STAGE, aBase, bBase, 1, tid);

    int slot = 0;
    for (int k = 0; k < NCHUNK; k++) {
        if (k < NCHUNK - 1) asm volatile("cp.async.wait_group 1;" ::: "memory");
        else                asm volatile("cp.async.wait_group 0;" ::: "memory");
        __syncthreads();

        uint32_t sb = sm + slot * STAGE;
        #pragma unroll
        for (int ks = 0; ks < 4; ks++) {
            uint32_t off = (((uint32_t)(ks << 5)) | ltb) ^ xk;
            uint32_t a[2][4], bf[4][4];
            ldsm4(a[0], sb + aA[0] + off);
            ldsm4(a[1], sb + aA[1] + off);
            #pragma unroll
            for (int nj = 0; nj < 4; nj++) ldsm4(bf[nj], sb + aB[nj] + off);
            #pragma unroll
            for (int mi = 0; mi < 2; mi++)
                #pragma unroll
                for (int ni = 0; ni < 8; ni++) {
                    int nj = ni >> 1, sel = ni & 1;
                    mma_s8(acc[mi][ni], a[mi], bf[nj][sel], bf[nj][sel + 2]);
                }
        }

        // issue prefetch for k+2 AFTER compute: all warps passed this iter's
        // __syncthreads, so nobody still reads slot (k+2)%3 == (k-1)%3.
        if (k + 2 < NCHUNK) {
            int s2 = slot + 2; if (s2 >= NSTAGE) s2 -= NSTAGE;
            load_stage(sm + s2 * STAGE, aBase, bBase, k + 2, tid);
        }
        slot = (slot + 1 == NSTAGE) ? 0 : slot + 1;
    }

    // epilogue
    #pragma unroll
    for (int mi = 0; mi < 2; mi++) {
        #pragma unroll
        for (int half = 0; half < 2; half++) {
            int b = b0 + wm * 32 + mi * 16 + (lane >> 2) + half * 8;
            int h = b / PADW, wp = b % PADW;
            bool valid = (h < HH) && (wp < WW);
            float bm = valid ? g_betamap[(size_t)n * HW + h * WW + wp] : 0.f;
            float* obase = out + (size_t)n * COUT * HW + h * WW + wp;
            if (valid) {
                #pragma unroll
                for (int ni = 0; ni < 8; ni++) {
                    #pragma unroll
                    for (int j2 = 0; j2 < 2; j2++) {
                        int co = cob + wn * 64 + ni * 8 + 2 * (lane & 3) + j2;
                        float v = ((float)acc[mi][ni][half * 2 + j2] + bias[co])
                                  * bm * g_alpha[co];
                        obase[(size_t)co * HW] = fmaxf(v, 0.f);
                    }
                }
            }
        }
    }
}

// ---------------- launcher ----------------
extern "C" void kernel_launch(void* const* d_in, const int* in_sizes, int n_in,
                              void* d_out, int out_size) {
    const float* x       = (const float*)d_in[0];
    const float* gamma   = (const float*)d_in[1];
    const float* beta_bn = (const float*)d_in[2];
    const float* Wt      = (const float*)d_in[3];
    const float* b       = (const float*)d_in[4];
    float* out = (float*)d_out;

    cudaFuncSetAttribute(conv_mma_kernel,
                         cudaFuncAttributeMaxDynamicSharedMemorySize, NSTAGE * STAGE);

    stats_kernel<<<CC, 256>>>(x, gamma, beta_bn);                 // launch 0
    binact_pack_kernel<<<(NHW + 255) / 256, 256>>>(x);            // launch 1
    boxwprep_kernel<<<BOX_BLOCKS + COUT, 256>>>(Wt);              // launch 2
    conv_mma_kernel<<<dim3(27, 2, NB), 256, NSTAGE * STAGE>>>(b, out);  // launch 3
}

// round 5
// speedup vs baseline: 10.8554x; 1.2689x over previous
#include <cuda_runtime.h>
#include <cuda_bf16.h>
#include <cstdint>

#define NB   32
#define CC   256
#define HH   56
#define WW   56
#define HW   3136
#define NHW  100352
#define COUT 256
#define KK   9
#define CIN_K 2304
#define PADW 58
#define XBP_PIX 3584
#define NBF  8          // images on bf16 path
#define NS8  16         // images on s8 path (8..23)

// ---------------- scratch (device globals; zero-init => padding stays 0) -------
__device__ float g_scale[CC];
__device__ float g_shift[CC];
__device__ float g_m[NHW];
__device__ float g_betamap[NHW];
__device__ float g_alpha[COUT];
__device__ int8_t        g_xb8 [(size_t)NB  * XBP_PIX * CC];
__device__ __nv_bfloat16 g_xbf [(size_t)NBF * XBP_PIX * CC];
__device__ uint32_t      g_xbits[(size_t)NB * XBP_PIX * 8];
__device__ int8_t        g_wb8 [(size_t)COUT * CIN_K];
__device__ __nv_bfloat16 g_wbf [(size_t)COUT * CIN_K];
__device__ uint32_t      g_wbits[(size_t)COUT * 72];

// ---------------- helpers ----------------
__device__ __forceinline__ uint32_t smem_u32(const void* p) {
    uint32_t a;
    asm("{ .reg .u64 t; cvta.to.shared.u64 t, %1; cvt.u32.u64 %0, t; }" : "=r"(a) : "l"(p));
    return a;
}
#define SWZ(o) ((o) ^ (((o) >> 3) & 0x70))
__device__ __forceinline__ void cp16(uint32_t dst, const void* src) {
    asm volatile("cp.async.cg.shared.global [%0], [%1], 16;" :: "r"(dst), "l"(src));
}
__device__ __forceinline__ void ldsm4(uint32_t* r, uint32_t addr) {
    asm volatile("ldmatrix.sync.aligned.m8n8.x4.shared.b16 {%0,%1,%2,%3}, [%4];"
                 : "=r"(r[0]), "=r"(r[1]), "=r"(r[2]), "=r"(r[3]) : "r"(addr));
}
__device__ __forceinline__ void mma_s8(int* d, const uint32_t* a, uint32_t b0, uint32_t b1) {
    asm volatile("mma.sync.aligned.m16n8k32.row.col.s32.s8.s8.s32 "
                 "{%0,%1,%2,%3}, {%4,%5,%6,%7}, {%8,%9}, {%0,%1,%2,%3};"
                 : "+r"(d[0]), "+r"(d[1]), "+r"(d[2]), "+r"(d[3])
                 : "r"(a[0]), "r"(a[1]), "r"(a[2]), "r"(a[3]), "r"(b0), "r"(b1));
}
__device__ __forceinline__ void mma_bf16(float* d, const uint32_t* a, uint32_t b0, uint32_t b1) {
    asm volatile("mma.sync.aligned.m16n8k16.row.col.f32.bf16.bf16.f32 "
                 "{%0,%1,%2,%3}, {%4,%5,%6,%7}, {%8,%9}, {%0,%1,%2,%3};"
                 : "+f"(d[0]), "+f"(d[1]), "+f"(d[2]), "+f"(d[3])
                 : "r"(a[0]), "r"(a[1]), "r"(a[2]), "r"(a[3]), "r"(b0), "r"(b1));
}

// ---------------- K1: BN batch stats -> affine ----------------
__global__ void stats_kernel(const float* __restrict__ x,
                             const float* __restrict__ gamma,
                             const float* __restrict__ beta_bn) {
    int c = blockIdx.x, tid = threadIdx.x;
    float s = 0.f, s2 = 0.f;
    for (int n = 0; n < NB; n++) {
        const float* p = x + ((size_t)n * CC + c) * HW;
        for (int i = tid; i < HW; i += blockDim.x) { float v = p[i]; s += v; s2 += v * v; }
    }
    __shared__ float sh[256], sh2[256];
    sh[tid] = s; sh2[tid] = s2; __syncthreads();
    for (int off = 128; off > 0; off >>= 1) {
        if (tid < off) { sh[tid] += sh[tid + off]; sh2[tid] += sh2[tid + off]; }
        __syncthreads();
    }
    if (tid == 0) {
        float mu  = sh[0] * (1.0f / (float)NHW);
        float var = sh2[0] * (1.0f / (float)NHW) - mu * mu;
        float inv = rsqrtf(var + 1e-4f);
        float sc  = gamma[c] * inv;
        g_scale[c] = sc;
        g_shift[c] = beta_bn[c] - mu * sc;
    }
}

// ------- K2: binarize -> s8 (all), bf16 (n<8), bitpack (all), + |xn| mean ------
__global__ void binact_pack_kernel(const float* __restrict__ x) {
    int gp = blockIdx.x * blockDim.x + threadIdx.x;
    if (gp >= NHW) return;
    int n = gp / HW, p = gp % HW;
    int h = p / WW, w = p % WW;
    const float* xp = x + (size_t)n * CC * HW + p;
    size_t ppix = (size_t)n * XBP_PIX + (h + 1) * PADW + (w + 1);
    int8_t* dst8 = g_xb8 + ppix * CC;
    __nv_bfloat16* dstbf = (n < NBF) ? (g_xbf + ppix * CC) : nullptr;
    uint32_t bits[8];
    float acc = 0.f;
    for (int c0 = 0; c0 < CC; c0 += 32) {
        int8_t buf[32];
        __nv_bfloat16 bbuf[32];
        uint32_t bw = 0;
        #pragma unroll
        for (int cc = 0; cc < 32; cc++) {
            int c = c0 + cc;
            float v = xp[(size_t)c * HW] * g_scale[c] + g_shift[c];
            acc += fabsf(v);
            int8_t s = (v > 0.f) ? (int8_t)1 : ((v < 0.f) ? (int8_t)-1 : (int8_t)0);
            buf[cc] = s;
            bbuf[cc] = __float2bfloat16((float)s);
            if (v < 0.f) bw |= (1u << cc);
        }
        bits[c0 >> 5] = bw;
        reinterpret_cast<uint4*>(dst8 + c0)[0] = reinterpret_cast<uint4*>(buf)[0];
        reinterpret_cast<uint4*>(dst8 + c0)[1] = reinterpret_cast<uint4*>(buf)[1];
        if (dstbf) {
            #pragma unroll
            for (int i = 0; i < 4; i++)
                reinterpret_cast<uint4*>(dstbf + c0)[i] = reinterpret_cast<uint4*>(bbuf)[i];
        }
    }
    uint32_t* bout = g_xbits + ppix * 8;
    reinterpret_cast<uint4*>(bout)[0] = reinterpret_cast<uint4*>(bits)[0];
    reinterpret_cast<uint4*>(bout)[1] = reinterpret_cast<uint4*>(bits)[1];
    g_m[gp] = acc * (1.0f / (float)CC);
}

// ------- K3: box filter + weight prep (s8 + bf16 + bits) + alpha ---------------
#define BOX_BLOCKS ((NHW + 255) / 256)
__global__ void boxwprep_kernel(const float* __restrict__ Wt) {
    if (blockIdx.x < BOX_BLOCKS) {
        int gp = blockIdx.x * blockDim.x + threadIdx.x;
        if (gp >= NHW) return;
        int n = gp / HW, p = gp % HW;
        int h = p / WW, w = p % WW;
        const float* mp = g_m + (size_t)n * HW;
        float s = 0.f;
        #pragma unroll
        for (int dh = -1; dh <= 1; dh++)
            #pragma unroll
            for (int dw = -1; dw <= 1; dw++) {
                int hh = h + dh, ww2 = w + dw;
                if (hh >= 0 && hh < HH && ww2 >= 0 && ww2 < WW) s += mp[hh * WW + ww2];
            }
        g_betamap[gp] = s * (1.0f / 9.0f);
    } else if (blockIdx.x < BOX_BLOCKS + COUT) {
        int co = blockIdx.x - BOX_BLOCKS, tid = threadIdx.x;
        const float* wp = Wt + (size_t)co * CIN_K;
        float s = 0.f;
        for (int i = tid; i < CIN_K; i += blockDim.x) {
            float v = wp[i];
            s += fabsf(v);
            int ci = i / KK, tap = i % KK;
            int8_t sv = (v > 0.f) ? (int8_t)1 : ((v < 0.f) ? (int8_t)-1 : (int8_t)0);
            g_wb8[(size_t)co * CIN_K + tap * CC + ci] = sv;
            g_wbf[(size_t)co * CIN_K + tap * CC + ci] = __float2bfloat16((float)sv);
        }
        __shared__ float sh[256];
        sh[tid] = s; __syncthreads();
        for (int off = 128; off > 0; off >>= 1) {
            if (tid < off) sh[tid] += sh[tid + off];
            __syncthreads();
        }
        if (tid == 0) g_alpha[co] = sh[0] * (1.0f / (float)CIN_K);
    } else {
        int idx = (blockIdx.x - BOX_BLOCKS - COUT) * 256 + threadIdx.x;  // < 18432
        int co = idx / 72, rem = idx % 72;
        int tap = rem / 8, wd = rem % 8;
        uint32_t bw = 0;
        const float* wp = Wt + (size_t)co * CIN_K;
        #pragma unroll
        for (int b = 0; b < 32; b++) {
            int ci = wd * 32 + b;
            if (wp[ci * KK + tap] < 0.f) bw |= (1u << b);
        }
        g_wbits[(size_t)co * 72 + tap * 8 + wd] = bw;
    }
}

// ---------------- conv path A: s8 IMMA (images 8..23) --------------------------
#define STAGE 32768
#define OFF_B 16384
#define NSTAGE 3

__device__ __forceinline__ void load_stage_s8(uint32_t sbase, const int8_t* aBase,
                                              const int8_t* bBase, int chunk, int tid) {
    int t = chunk >> 1, q = chunk & 1;
    int off_t = (t / 3) * PADW + (t % 3);
    const int8_t* a0 = aBase + (size_t)off_t * CC + q * 128;
    const int8_t* bs = bBase + t * CC + q * 128;
    #pragma unroll
    for (int i = 0; i < 4; i++) {
        int slot = tid + 256 * i; int row = slot >> 3, c16 = slot & 7;
        cp16(sbase + SWZ(row * 128 + c16 * 16), a0 + (size_t)row * CC + c16 * 16);
    }
    #pragma unroll
    for (int i = 0; i < 4; i++) {
        int slot = tid + 256 * i; int row = slot >> 3, c16 = slot & 7;
        cp16(sbase + OFF_B + SWZ(row * 128 + c16 * 16), bs + (size_t)row * CIN_K + c16 * 16);
    }
    asm volatile("cp.async.commit_group;" ::: "memory");
}

__global__ void __launch_bounds__(256, 2)
conv_s8_kernel(const float* __restrict__ bias, float* __restrict__ out) {
    extern __shared__ __align__(1024) char smem[];
    uint32_t sm = smem_u32(smem);
    int tid = threadIdx.x, wid = tid >> 5, lane = tid & 31;
    int b0  = blockIdx.x * 128;
    int cob = blockIdx.y * 128;
    int n   = blockIdx.z + NBF;
    int wm = wid & 3, wn = wid >> 2;

    const int8_t* aBase = g_xb8 + ((size_t)n * XBP_PIX + b0) * CC;
    const int8_t* bBase = g_wb8 + (size_t)cob * CIN_K;

    int lrow = (lane & 7) + ((lane >> 3) & 1) * 8;
    uint32_t ltb = (uint32_t)((lane >> 4) * 16);
    uint32_t xk  = (uint32_t)((lane & 7) << 4);
    uint32_t aA[2], aB[4];
    #pragma unroll
    for (int mi = 0; mi < 2; mi++) aA[mi] = (uint32_t)((wm * 32 + mi * 16 + lrow) * 128);
    #pragma unroll
    for (int nj = 0; nj < 4; nj++) aB[nj] = (uint32_t)(OFF_B + (wn * 64 + nj * 16 + lrow) * 128);

    int acc[2][8][4];
    #pragma unroll
    for (int mi = 0; mi < 2; mi++)
        #pragma unroll
        for (int ni = 0; ni < 8; ni++)
            #pragma unroll
            for (int j = 0; j < 4; j++) acc[mi][ni][j] = 0;

    load_stage_s8(sm + 0 * STAGE, aBase, bBase, 0, tid);
    load_stage_s8(sm + 1 * STAGE, aBase, bBase, 1, tid);

    int slot = 0;
    const int NCH = 18;
    for (int k = 0; k < NCH; k++) {
        if (k < NCH - 1) asm volatile("cp.async.wait_group 1;" ::: "memory");
        else             asm volatile("cp.async.wait_group 0;" ::: "memory");
        __syncthreads();
        uint32_t sb = sm + slot * STAGE;
        #pragma unroll
        for (int ks = 0; ks < 4; ks++) {
            uint32_t off = (((uint32_t)(ks << 5)) | ltb) ^ xk;
            uint32_t a[2][4], bf[4][4];
            ldsm4(a[0], sb + aA[0] + off);
            ldsm4(a[1], sb + aA[1] + off);
            #pragma unroll
            for (int nj = 0; nj < 4; nj++) ldsm4(bf[nj], sb + aB[nj] + off);
            #pragma unroll
            for (int mi = 0; mi < 2; mi++)
                #pragma unroll
                for (int ni = 0; ni < 8; ni++) {
                    int nj = ni >> 1, sel = ni & 1;
                    mma_s8(acc[mi][ni], a[mi], bf[nj][sel], bf[nj][sel + 2]);
                }
        }
        if (k + 2 < NCH) {
            int s2 = slot + 2; if (s2 >= NSTAGE) s2 -= NSTAGE;
            load_stage_s8(sm + s2 * STAGE, aBase, bBase, k + 2, tid);
        }
        slot = (slot + 1 == NSTAGE) ? 0 : slot + 1;
    }

    #pragma unroll
    for (int mi = 0; mi < 2; mi++)
        #pragma unroll
        for (int half = 0; half < 2; half++) {
            int b = b0 + wm * 32 + mi * 16 + (lane >> 2) + half * 8;
            int h = b / PADW, wp = b % PADW;
            bool valid = (h < HH) && (wp < WW);
            float bm = valid ? g_betamap[(size_t)n * HW + h * WW + wp] : 0.f;
            float* obase = out + (size_t)n * COUT * HW + h * WW + wp;
            if (valid) {
                #pragma unroll
                for (int ni = 0; ni < 8; ni++)
                    #pragma unroll
                    for (int j2 = 0; j2 < 2; j2++) {
                        int co = cob + wn * 64 + ni * 8 + 2 * (lane & 3) + j2;
                        float v = ((float)acc[mi][ni][half * 2 + j2] + bias[co])
                                  * bm * g_alpha[co];
                        obase[(size_t)co * HW] = fmaxf(v, 0.f);
                    }
            }
        }
}

// ---------------- conv path B: bf16 HMMA (images 0..7) -------------------------
__device__ __forceinline__ void load_stage_bf(uint32_t sbase, const __nv_bfloat16* aBase,
                                              const __nv_bfloat16* bBase, int chunk, int tid) {
    int t = chunk >> 2, q = chunk & 3;                   // 64-channel group
    int off_t = (t / 3) * PADW + (t % 3);
    const __nv_bfloat16* a0 = aBase + (size_t)off_t * CC + q * 64;
    const __nv_bfloat16* bs = bBase + t * CC + q * 64;
    #pragma unroll
    for (int i = 0; i < 4; i++) {
        int slot = tid + 256 * i; int row = slot >> 3, c16 = slot & 7;
        cp16(sbase + SWZ(row * 128 + c16 * 16),
             (const char*)(a0 + (size_t)row * CC) + c16 * 16);
    }
    #pragma unroll
    for (int i = 0; i < 4; i++) {
        int slot = tid + 256 * i; int row = slot >> 3, c16 = slot & 7;
        cp16(sbase + OFF_B + SWZ(row * 128 + c16 * 16),
             (const char*)(bs + (size_t)row * CIN_K) + c16 * 16);
    }
    asm volatile("cp.async.commit_group;" ::: "memory");
}

__global__ void __launch_bounds__(256, 2)
conv_bf16_kernel(const float* __restrict__ bias, float* __restrict__ out) {
    extern __shared__ __align__(1024) char smem[];
    uint32_t sm = smem_u32(smem);
    int tid = threadIdx.x, wid = tid >> 5, lane = tid & 31;
    int b0  = blockIdx.x * 128;
    int cob = blockIdx.y * 128;
    int n   = blockIdx.z;                                // 0..7
    int wm = wid & 3, wn = wid >> 2;

    const __nv_bfloat16* aBase = g_xbf + ((size_t)n * XBP_PIX + b0) * CC;
    const __nv_bfloat16* bBase = g_wbf + (size_t)cob * CIN_K;

    int lrow = (lane & 7) + ((lane >> 3) & 1) * 8;
    uint32_t ltb = (uint32_t)((lane >> 4) * 16);
    uint32_t xk  = (uint32_t)((lane & 7) << 4);
    uint32_t aA[2], aB[4];
    #pragma unroll
    for (int mi = 0; mi < 2; mi++) aA[mi] = (uint32_t)((wm * 32 + mi * 16 + lrow) * 128);
    #pragma unroll
    for (int nj = 0; nj < 4; nj++) aB[nj] = (uint32_t)(OFF_B + (wn * 64 + nj * 16 + lrow) * 128);

    float acc[2][8][4];
    #pragma unroll
    for (int mi = 0; mi < 2; mi++)
        #pragma unroll
        for (int ni = 0; ni < 8; ni++)
            #pragma unroll
            for (int j = 0; j < 4; j++) acc[mi][ni][j] = 0.f;

    load_stage_bf(sm + 0 * STAGE, aBase, bBase, 0, tid);
    load_stage_bf(sm + 1 * STAGE, aBase, bBase, 1, tid);

    int slot = 0;
    const int NCH = 36;
    for (int k = 0; k < NCH; k++) {
        if (k < NCH - 1) asm volatile("cp.async.wait_group 1;" ::: "memory");
        else             asm volatile("cp.async.wait_group 0;" ::: "memory");
        __syncthreads();
        uint32_t sb = sm + slot * STAGE;
        #pragma unroll
        for (int ks = 0; ks < 4; ks++) {                 // 16 halves per kstep
            uint32_t off = (((uint32_t)(ks << 5)) | ltb) ^ xk;
            uint32_t a[2][4], bf[4][4];
            ldsm4(a[0], sb + aA[0] + off);
            ldsm4(a[1], sb + aA[1] + off);
            #pragma unroll
            for (int nj = 0; nj < 4; nj++) ldsm4(bf[nj], sb + aB[nj] + off);
            #pragma unroll
            for (int mi = 0; mi < 2; mi++)
                #pragma unroll
                for (int ni = 0; ni < 8; ni++) {
                    int nj = ni >> 1, sel = ni & 1;
                    mma_bf16(acc[mi][ni], a[mi], bf[nj][sel], bf[nj][sel + 2]);
                }
        }
        if (k + 2 < NCH) {
            int s2 = slot + 2; if (s2 >= NSTAGE) s2 -= NSTAGE;
            load_stage_bf(sm + s2 * STAGE, aBase, bBase, k + 2, tid);
        }
        slot = (slot + 1 == NSTAGE) ? 0 : slot + 1;
    }

    #pragma unroll
    for (int mi = 0; mi < 2; mi++)
        #pragma unroll
        for (int half = 0; half < 2; half++) {
            int b = b0 + wm * 32 + mi * 16 + (lane >> 2) + half * 8;
            int h = b / PADW, wp = b % PADW;
            bool valid = (h < HH) && (wp < WW);
            float bm = valid ? g_betamap[(size_t)n * HW + h * WW + wp] : 0.f;
            float* obase = out + (size_t)n * COUT * HW + h * WW + wp;
            if (valid) {
                #pragma unroll
                for (int ni = 0; ni < 8; ni++)
                    #pragma unroll
                    for (int j2 = 0; j2 < 2; j2++) {
                        int co = cob + wn * 64 + ni * 8 + 2 * (lane & 3) + j2;
                        float v = (acc[mi][ni][half * 2 + j2] + bias[co])
                                  * bm * g_alpha[co];
                        obase[(size_t)co * HW] = fmaxf(v, 0.f);
                    }
            }
        }
}

// ---------------- conv path C: XNOR+POPC (images 24..31) -----------------------
#define OPITCH 29
__global__ void __launch_bounds__(256)
conv_popc_kernel(const float* __restrict__ bias, float* __restrict__ out) {
    int h = blockIdx.x;                  // 0..55
    int n = blockIdx.y + NBF + NS8;      // 24..31
    int co = threadIdx.x;
    __shared__ uint32_t s_act[3][58][8];
    __shared__ float s_out[256 * OPITCH];

    for (int i = co; i < 3 * 58 * 8; i += 256) {
        int dr = i / (58 * 8), rem = i % (58 * 8);
        int xc = rem >> 3, wd = rem & 7;
        s_act[dr][xc][wd] = g_xbits[((size_t)n * XBP_PIX + (h + dr) * PADW + xc) * 8 + wd];
    }
    uint32_t wreg[72];
    {
        const uint4* wsrc = reinterpret_cast<const uint4*>(g_wbits + (size_t)co * 72);
        #pragma unroll
        for (int i = 0; i < 18; i++) reinterpret_cast<uint4*>(wreg)[i] = wsrc[i];
    }
    float alpha = g_alpha[co];
    float bi = bias[co];
    __syncthreads();

    bool vr0 = (h > 0), vr2 = (h < HH - 1);
    int nvr = 1 + (int)vr0 + (int)vr2;
    float* obaseN = out + (size_t)n * COUT * HW + h * WW;
    const float* bmrow = g_betamap + (size_t)n * HW + h * WW;

    for (int wh = 0; wh < 2; wh++) {
        int w0 = wh * 28;
        for (int w = w0; w < w0 + 28; w++) {
            bool vl = (w > 0), vrt = (w < WW - 1);
            int sp = 0;
            #pragma unroll
            for (int dr = 0; dr < 3; dr++) {
                if (dr == 0 && !vr0) continue;
                if (dr == 2 && !vr2) continue;
                #pragma unroll
                for (int dc = 0; dc < 3; dc++) {
                    if (dc == 0 && !vl) continue;
                    if (dc == 2 && !vrt) continue;
                    const uint32_t* aw = s_act[dr][w + dc];
                    const uint32_t* wr = &wreg[(dr * 3 + dc) * 8];
                    #pragma unroll
                    for (int wd = 0; wd < 8; wd++) sp += __popc(aw[wd] ^ wr[wd]);
                }
            }
            int V = nvr * (1 + (int)vl + (int)vrt);
            float dot = (float)(256 * V - 2 * sp);
            s_out[co * OPITCH + (w - w0)] = fmaxf((dot + bi) * bmrow[w] * alpha, 0.f);
        }
        __syncthreads();
        int lane = co & 31, wd2 = co >> 5;
        for (int c2 = wd2; c2 < 256; c2 += 8) {
            if (lane < 28) obaseN[(size_t)c2 * HW + w0 + lane] = s_out[c2 * OPITCH + lane];
        }
        __syncthreads();
    }
}

// ---------------- launcher ----------------
extern "C" void kernel_launch(void* const* d_in, const int* in_sizes, int n_in,
                              void* d_out, int out_size) {
    const float* x       = (const float*)d_in[0];
    const float* gamma   = (const float*)d_in[1];
    const float* beta_bn = (const float*)d_in[2];
    const float* Wt      = (const float*)d_in[3];
    const float* b       = (const float*)d_in[4];
    float* out = (float*)d_out;

    cudaFuncSetAttribute(conv_s8_kernel,
                         cudaFuncAttributeMaxDynamicSharedMemorySize, NSTAGE * STAGE);
    cudaFuncSetAttribute(conv_bf16_kernel,
                         cudaFuncAttributeMaxDynamicSharedMemorySize, NSTAGE * STAGE);

    stats_kernel<<<CC, 256>>>(x, gamma, beta_bn);
    binact_pack_kernel<<<(NHW + 255) / 256, 256>>>(x);
    boxwprep_kernel<<<BOX_BLOCKS + COUT + 72, 256>>>(Wt);
    conv_bf16_kernel<<<dim3(27, 2, NBF), 256, NSTAGE * STAGE>>>(b, out);
    conv_s8_kernel<<<dim3(27, 2, NS8), 256, NSTAGE * STAGE>>>(b, out);
    conv_popc_kernel<<<dim3(HH, NB - NBF - NS8), 256>>>(b, out);
}

// round 6
// speedup vs baseline: 17.9244x; 1.6512x over previous
#include <cuda_runtime.h>
#include <cuda_bf16.h>
#include <cstdint>

#define NB   32
#define CC   256
#define HH   56
#define WW   56
#define HW   3136
#define NHW  100352
#define COUT 256
#define KK   9
#define CIN_K 2304
#define PADW 58
#define XBP_PIX 3584

// ---------------- scratch (device globals; zero-init => padding stays 0) -------
__device__ float g_scale[CC];
__device__ float g_shift[CC];
__device__ float g_m[NHW];
__device__ float g_betamap[NHW];
__device__ float g_alpha[COUT];
__device__ __nv_bfloat16 g_xbf[(size_t)NB * XBP_PIX * CC];   // [n][padded pix][c]
__device__ __nv_bfloat16 g_wbf[(size_t)COUT * CIN_K];        // [cout][tap*256+ci]

// ---------------- helpers ----------------
__device__ __forceinline__ uint32_t smem_u32(const void* p) {
    uint32_t a;
    asm("{ .reg .u64 t; cvta.to.shared.u64 t, %1; cvt.u32.u64 %0, t; }" : "=r"(a) : "l"(p));
    return a;
}
#define SWZ(o) ((o) ^ (((o) >> 3) & 0x70))
__device__ __forceinline__ void cp16(uint32_t dst, const void* src) {
    asm volatile("cp.async.cg.shared.global [%0], [%1], 16;" :: "r"(dst), "l"(src));
}
__device__ __forceinline__ void ldsm4(uint32_t* r, uint32_t addr) {
    asm volatile("ldmatrix.sync.aligned.m8n8.x4.shared.b16 {%0,%1,%2,%3}, [%4];"
                 : "=r"(r[0]), "=r"(r[1]), "=r"(r[2]), "=r"(r[3]) : "r"(addr));
}
__device__ __forceinline__ void mma_bf16(float* d, const uint32_t* a, uint32_t b0, uint32_t b1) {
    asm volatile("mma.sync.aligned.m16n8k16.row.col.f32.bf16.bf16.f32 "
                 "{%0,%1,%2,%3}, {%4,%5,%6,%7}, {%8,%9}, {%0,%1,%2,%3};"
                 : "+f"(d[0]), "+f"(d[1]), "+f"(d[2]), "+f"(d[3])
                 : "r"(a[0]), "r"(a[1]), "r"(a[2]), "r"(a[3]), "r"(b0), "r"(b1));
}

// ---------------- K1: BN batch stats -> affine ----------------
__global__ void stats_kernel(const float* __restrict__ x,
                             const float* __restrict__ gamma,
                             const float* __restrict__ beta_bn) {
    int c = blockIdx.x, tid = threadIdx.x;
    float s = 0.f, s2 = 0.f;
    for (int n = 0; n < NB; n++) {
        const float* p = x + ((size_t)n * CC + c) * HW;
        for (int i = tid; i < HW; i += blockDim.x) { float v = p[i]; s += v; s2 += v * v; }
    }
    __shared__ float sh[256], sh2[256];
    sh[tid] = s; sh2[tid] = s2; __syncthreads();
    for (int off = 128; off > 0; off >>= 1) {
        if (tid < off) { sh[tid] += sh[tid + off]; sh2[tid] += sh2[tid + off]; }
        __syncthreads();
    }
    if (tid == 0) {
        float mu  = sh[0] * (1.0f / (float)NHW);
        float var = sh2[0] * (1.0f / (float)NHW) - mu * mu;
        float inv = rsqrtf(var + 1e-4f);
        float sc  = gamma[c] * inv;
        g_scale[c] = sc;
        g_shift[c] = beta_bn[c] - mu * sc;
    }
}

// ------- K2: binarize -> bf16 channels-last padded, + |xn| mean ----------------
__global__ void binact_pack_kernel(const float* __restrict__ x) {
    int gp = blockIdx.x * blockDim.x + threadIdx.x;
    if (gp >= NHW) return;
    int n = gp / HW, p = gp % HW;
    int h = p / WW, w = p % WW;
    const float* xp = x + (size_t)n * CC * HW + p;
    __nv_bfloat16* dst = g_xbf + ((size_t)n * XBP_PIX + (h + 1) * PADW + (w + 1)) * CC;
    float acc = 0.f;
    for (int c0 = 0; c0 < CC; c0 += 32) {
        __nv_bfloat16 bbuf[32];
        #pragma unroll
        for (int cc = 0; cc < 32; cc++) {
            int c = c0 + cc;
            float v = xp[(size_t)c * HW] * g_scale[c] + g_shift[c];
            acc += fabsf(v);
            float s = (v > 0.f) ? 1.f : ((v < 0.f) ? -1.f : 0.f);
            bbuf[cc] = __float2bfloat16(s);
        }
        #pragma unroll
        for (int i = 0; i < 4; i++)
            reinterpret_cast<uint4*>(dst + c0)[i] = reinterpret_cast<uint4*>(bbuf)[i];
    }
    g_m[gp] = acc * (1.0f / (float)CC);
}

// ------- K3: box filter + weight prep (bf16, tap-major) + alpha ----------------
#define BOX_BLOCKS ((NHW + 255) / 256)
__global__ void boxwprep_kernel(const float* __restrict__ Wt) {
    if (blockIdx.x < BOX_BLOCKS) {
        int gp = blockIdx.x * blockDim.x + threadIdx.x;
        if (gp >= NHW) return;
        int n = gp / HW, p = gp % HW;
        int h = p / WW, w = p % WW;
        const float* mp = g_m + (size_t)n * HW;
        float s = 0.f;
        #pragma unroll
        for (int dh = -1; dh <= 1; dh++)
            #pragma unroll
            for (int dw = -1; dw <= 1; dw++) {
                int hh = h + dh, ww2 = w + dw;
                if (hh >= 0 && hh < HH && ww2 >= 0 && ww2 < WW) s += mp[hh * WW + ww2];
            }
        g_betamap[gp] = s * (1.0f / 9.0f);
    } else {
        int co = blockIdx.x - BOX_BLOCKS, tid = threadIdx.x;
        const float* wp = Wt + (size_t)co * CIN_K;
        float s = 0.f;
        for (int i = tid; i < CIN_K; i += blockDim.x) {
            float v = wp[i];
            s += fabsf(v);
            int ci = i / KK, tap = i % KK;
            float sv = (v > 0.f) ? 1.f : ((v < 0.f) ? -1.f : 0.f);
            g_wbf[(size_t)co * CIN_K + tap * CC + ci] = __float2bfloat16(sv);
        }
        __shared__ float sh[256];
        sh[tid] = s; __syncthreads();
        for (int off = 128; off > 0; off >>= 1) {
            if (tid < off) sh[tid] += sh[tid + off];
            __syncthreads();
        }
        if (tid == 0) g_alpha[co] = sh[0] * (1.0f / (float)CIN_K);
    }
}

// ---------------- K4: bf16 HMMA implicit-GEMM conv, 3-stage pipeline -----------
#define STAGE 32768
#define OFF_B 16384
#define NSTAGE 3
#define NCH 36           // 9 taps x 4 chunks of 64 channels

__device__ __forceinline__ void load_stage_bf(uint32_t sbase, const __nv_bfloat16* aBase,
                                              const __nv_bfloat16* bBase, int chunk, int tid) {
    int t = chunk >> 2, q = chunk & 3;                   // tap, 64-channel group
    int off_t = (t / 3) * PADW + (t % 3);
    const __nv_bfloat16* a0 = aBase + (size_t)off_t * CC + q * 64;
    const __nv_bfloat16* bs = bBase + t * CC + q * 64;
    #pragma unroll
    for (int i = 0; i < 4; i++) {       // A: 128 rows x 128B
        int slot = tid + 256 * i; int row = slot >> 3, c16 = slot & 7;
        cp16(sbase + SWZ(row * 128 + c16 * 16),
             (const char*)(a0 + (size_t)row * CC) + c16 * 16);
    }
    #pragma unroll
    for (int i = 0; i < 4; i++) {       // B: 128 couts x 128B
        int slot = tid + 256 * i; int row = slot >> 3, c16 = slot & 7;
        cp16(sbase + OFF_B + SWZ(row * 128 + c16 * 16),
             (const char*)(bs + (size_t)row * CIN_K) + c16 * 16);
    }
    asm volatile("cp.async.commit_group;" ::: "memory");
}

__global__ void __launch_bounds__(256, 2)
conv_bf16_kernel(const float* __restrict__ bias, float* __restrict__ out) {
    extern __shared__ __align__(1024) char smem[];
    uint32_t sm = smem_u32(smem);
    int tid = threadIdx.x, wid = tid >> 5, lane = tid & 31;
    int b0  = blockIdx.x * 128;
    int cob = blockIdx.y * 128;
    int n   = blockIdx.z;
    int wm = wid & 3, wn = wid >> 2;    // warp tile: 32 pixels x 64 couts

    const __nv_bfloat16* aBase = g_xbf + ((size_t)n * XBP_PIX + b0) * CC;
    const __nv_bfloat16* bBase = g_wbf + (size_t)cob * CIN_K;

    int lrow = (lane & 7) + ((lane >> 3) & 1) * 8;
    uint32_t ltb = (uint32_t)((lane >> 4) * 16);
    uint32_t xk  = (uint32_t)((lane & 7) << 4);
    uint32_t aA[2], aB[4];
    #pragma unroll
    for (int mi = 0; mi < 2; mi++) aA[mi] = (uint32_t)((wm * 32 + mi * 16 + lrow) * 128);
    #pragma unroll
    for (int nj = 0; nj < 4; nj++) aB[nj] = (uint32_t)(OFF_B + (wn * 64 + nj * 16 + lrow) * 128);

    float acc[2][8][4];
    #pragma unroll
    for (int mi = 0; mi < 2; mi++)
        #pragma unroll
        for (int ni = 0; ni < 8; ni++)
            #pragma unroll
            for (int j = 0; j < 4; j++) acc[mi][ni][j] = 0.f;

    load_stage_bf(sm + 0 * STAGE, aBase, bBase, 0, tid);
    load_stage_bf(sm + 1 * STAGE, aBase, bBase, 1, tid);

    int slot = 0;
    for (int k = 0; k < NCH; k++) {
        if (k < NCH - 1) asm volatile("cp.async.wait_group 1;" ::: "memory");
        else             asm volatile("cp.async.wait_group 0;" ::: "memory");
        __syncthreads();

        // prefetch k+2 into slot (k-1)%3 BEFORE compute: the barrier above
        // guarantees every warp finished computing chunk k-1, so its slot is
        // free; the load then overlaps this chunk's MMAs.
        if (k + 2 < NCH) {
            int s2 = slot + 2; if (s2 >= NSTAGE) s2 -= NSTAGE;
            load_stage_bf(sm + s2 * STAGE, aBase, bBase, k + 2, tid);
        }

        uint32_t sb = sm + slot * STAGE;
        #pragma unroll
        for (int ks = 0; ks < 4; ks++) {                 // 16-ch halves
            uint32_t off = (((uint32_t)(ks << 5)) | ltb) ^ xk;
            uint32_t a[2][4], bf[4][4];
            ldsm4(a[0], sb + aA[0] + off);
            ldsm4(a[1], sb + aA[1] + off);
            #pragma unroll
            for (int nj = 0; nj < 4; nj++) ldsm4(bf[nj], sb + aB[nj] + off);
            #pragma unroll
            for (int mi = 0; mi < 2; mi++)
                #pragma unroll
                for (int ni = 0; ni < 8; ni++) {
                    int nj = ni >> 1, sel = ni & 1;
                    mma_bf16(acc[mi][ni], a[mi], bf[nj][sel], bf[nj][sel + 2]);
                }
        }
        slot = (slot + 1 == NSTAGE) ? 0 : slot + 1;
    }

    #pragma unroll
    for (int mi = 0; mi < 2; mi++)
        #pragma unroll
        for (int half = 0; half < 2; half++) {
            int b = b0 + wm * 32 + mi * 16 + (lane >> 2) + half * 8;
            int h = b / PADW, wp = b % PADW;
            bool valid = (h < HH) && (wp < WW);
            float bm = valid ? g_betamap[(size_t)n * HW + h * WW + wp] : 0.f;
            float* obase = out + (size_t)n * COUT * HW + h * WW + wp;
            if (valid) {
                #pragma unroll
                for (int ni = 0; ni < 8; ni++)
                    #pragma unroll
                    for (int j2 = 0; j2 < 2; j2++) {
                        int co = cob + wn * 64 + ni * 8 + 2 * (lane & 3) + j2;
                        float v = (acc[mi][ni][half * 2 + j2] + bias[co])
                                  * bm * g_alpha[co];
                        obase[(size_t)co * HW] = fmaxf(v, 0.f);
                    }
            }
        }
}

// ---------------- launcher ----------------
extern "C" void kernel_launch(void* const* d_in, const int* in_sizes, int n_in,
                              void* d_out, int out_size) {
    const float* x       = (const float*)d_in[0];
    const float* gamma   = (const float*)d_in[1];
    const float* beta_bn = (const float*)d_in[2];
    const float* Wt      = (const float*)d_in[3];
    const float* b       = (const float*)d_in[4];
    float* out = (float*)d_out;

    cudaFuncSetAttribute(conv_bf16_kernel,
                         cudaFuncAttributeMaxDynamicSharedMemorySize, NSTAGE * STAGE);

    stats_kernel<<<CC, 256>>>(x, gamma, beta_bn);
    binact_pack_kernel<<<(NHW + 255) / 256, 256>>>(x);
    boxwprep_kernel<<<BOX_BLOCKS + COUT, 256>>>(Wt);
    conv_bf16_kernel<<<dim3(27, 2, NB), 256, NSTAGE * STAGE>>>(b, out);
}

// round 7
// speedup vs baseline: 18.3125x; 1.0216x over previous
#include <cuda_runtime.h>
#include <cuda_bf16.h>
#include <cstdint>

#define NB   32
#define CC   256
#define HH   56
#define WW   56
#define HW   3136
#define NHW  100352
#define COUT 256
#define KK   9
#define CIN_K 2304
#define PADW 58
#define XBP_PIX 3584

// ---------------- scratch (device globals; zero-init => padding stays 0) -------
__device__ float g_psum[CC * 8 * 2];
__device__ float g_scale[CC];
__device__ float g_shift[CC];
__device__ float g_m[NHW];
__device__ float g_betamap[NHW];
__device__ float g_alpha[COUT];
__device__ __nv_bfloat16 g_xbf[(size_t)NB * XBP_PIX * CC];   // [n][padded pix][c]
__device__ __nv_bfloat16 g_wbf[(size_t)COUT * CIN_K];        // [cout][tap*256+ci]

// ---------------- helpers ----------------
__device__ __forceinline__ uint32_t smem_u32(const void* p) {
    uint32_t a;
    asm("{ .reg .u64 t; cvta.to.shared.u64 t, %1; cvt.u32.u64 %0, t; }" : "=r"(a) : "l"(p));
    return a;
}
#define SWZ(o) ((o) ^ (((o) >> 3) & 0x70))
__device__ __forceinline__ void cp16(uint32_t dst, const void* src) {
    asm volatile("cp.async.cg.shared.global [%0], [%1], 16;" :: "r"(dst), "l"(src));
}
__device__ __forceinline__ void ldsm4(uint32_t* r, uint32_t addr) {
    asm volatile("ldmatrix.sync.aligned.m8n8.x4.shared.b16 {%0,%1,%2,%3}, [%4];"
                 : "=r"(r[0]), "=r"(r[1]), "=r"(r[2]), "=r"(r[3]) : "r"(addr));
}
__device__ __forceinline__ void mma_bf16(float* d, const uint32_t* a, uint32_t b0, uint32_t b1) {
    asm volatile("mma.sync.aligned.m16n8k16.row.col.f32.bf16.bf16.f32 "
                 "{%0,%1,%2,%3}, {%4,%5,%6,%7}, {%8,%9}, {%0,%1,%2,%3};"
                 : "+f"(d[0]), "+f"(d[1]), "+f"(d[2]), "+f"(d[3])
                 : "r"(a[0]), "r"(a[1]), "r"(a[2]), "r"(a[3]), "r"(b0), "r"(b1));
}

// ---------------- K1a/K1b: BN batch stats (two-phase) ----------------
__global__ void stats_part_kernel(const float* __restrict__ x) {
    int c = blockIdx.x, sl = blockIdx.y, tid = threadIdx.x;
    float s = 0.f, s2 = 0.f;
    for (int n = sl * 4; n < sl * 4 + 4; n++) {
        const float* p = x + ((size_t)n * CC + c) * HW;
        for (int i = tid; i < HW; i += blockDim.x) { float v = p[i]; s += v; s2 += v * v; }
    }
    __shared__ float sh[256], sh2[256];
    sh[tid] = s; sh2[tid] = s2; __syncthreads();
    for (int off = 128; off > 0; off >>= 1) {
        if (tid < off) { sh[tid] += sh[tid + off]; sh2[tid] += sh2[tid + off]; }
        __syncthreads();
    }
    if (tid == 0) { g_psum[(c * 8 + sl) * 2] = sh[0]; g_psum[(c * 8 + sl) * 2 + 1] = sh2[0]; }
}
__global__ void stats_final_kernel(const float* __restrict__ gamma,
                                   const float* __restrict__ beta_bn) {
    int c = threadIdx.x;
    float s = 0.f, s2 = 0.f;
    #pragma unroll
    for (int i = 0; i < 8; i++) { s += g_psum[(c * 8 + i) * 2]; s2 += g_psum[(c * 8 + i) * 2 + 1]; }
    float mu  = s * (1.0f / (float)NHW);
    float var = s2 * (1.0f / (float)NHW) - mu * mu;
    float inv = rsqrtf(var + 1e-4f);
    float sc  = gamma[c] * inv;
    g_scale[c] = sc;
    g_shift[c] = beta_bn[c] - mu * sc;
}

// ------- K2: binarize -> bf16 channels-last padded, + |xn| mean ----------------
__global__ void binact_pack_kernel(const float* __restrict__ x) {
    int gp = blockIdx.x * blockDim.x + threadIdx.x;
    if (gp >= NHW) return;
    int n = gp / HW, p = gp % HW;
    int h = p / WW, w = p % WW;
    const float* xp = x + (size_t)n * CC * HW + p;
    __nv_bfloat16* dst = g_xbf + ((size_t)n * XBP_PIX + (h + 1) * PADW + (w + 1)) * CC;
    float acc = 0.f;
    for (int c0 = 0; c0 < CC; c0 += 32) {
        __nv_bfloat16 bbuf[32];
        #pragma unroll
        for (int cc = 0; cc < 32; cc++) {
            int c = c0 + cc;
            float v = xp[(size_t)c * HW] * g_scale[c] + g_shift[c];
            acc += fabsf(v);
            float s = (v > 0.f) ? 1.f : ((v < 0.f) ? -1.f : 0.f);
            bbuf[cc] = __float2bfloat16(s);
        }
        #pragma unroll
        for (int i = 0; i < 4; i++)
            reinterpret_cast<uint4*>(dst + c0)[i] = reinterpret_cast<uint4*>(bbuf)[i];
    }
    g_m[gp] = acc * (1.0f / (float)CC);
}

// ------- K3: box filter + weight prep (bf16, tap-major) + alpha ----------------
#define BOX_BLOCKS ((NHW + 255) / 256)
__global__ void boxwprep_kernel(const float* __restrict__ Wt) {
    if (blockIdx.x < BOX_BLOCKS) {
        int gp = blockIdx.x * blockDim.x + threadIdx.x;
        if (gp >= NHW) return;
        int n = gp / HW, p = gp % HW;
        int h = p / WW, w = p % WW;
        const float* mp = g_m + (size_t)n * HW;
        float s = 0.f;
        #pragma unroll
        for (int dh = -1; dh <= 1; dh++)
            #pragma unroll
            for (int dw = -1; dw <= 1; dw++) {
                int hh = h + dh, ww2 = w + dw;
                if (hh >= 0 && hh < HH && ww2 >= 0 && ww2 < WW) s += mp[hh * WW + ww2];
            }
        g_betamap[gp] = s * (1.0f / 9.0f);
    } else {
        int co = blockIdx.x - BOX_BLOCKS, tid = threadIdx.x;
        const float* wp = Wt + (size_t)co * CIN_K;
        float s = 0.f;
        for (int i = tid; i < CIN_K; i += blockDim.x) {
            float v = wp[i];
            s += fabsf(v);
            int ci = i / KK, tap = i % KK;
            float sv = (v > 0.f) ? 1.f : ((v < 0.f) ? -1.f : 0.f);
            g_wbf[(size_t)co * CIN_K + tap * CC + ci] = __float2bfloat16(sv);
        }
        __shared__ float sh[256];
        sh[tid] = s; __syncthreads();
        for (int off = 128; off > 0; off >>= 1) {
            if (tid < off) sh[tid] += sh[tid + off];
            __syncthreads();
        }
        if (tid == 0) g_alpha[co] = sh[0] * (1.0f / (float)CIN_K);
    }
}

// ---------------- K4: bf16 HMMA conv, CTA 128px x 256co, warp 64x64 ------------
#define STAGE 49152          // A 16KB + B 32KB
#define OFF_B 16384
#define NSTAGE 2
#define NCH 36               // 9 taps x 4 chunks of 64 channels
#define OFF_AB (NSTAGE * STAGE)
#define SMEM_TOT (OFF_AB + 2048)

__device__ __forceinline__ void load_stage_bf(uint32_t sbase, const __nv_bfloat16* aBase,
                                              const __nv_bfloat16* bBase, int chunk, int tid) {
    int t = chunk >> 2, q = chunk & 3;                   // tap, 64-channel group
    int off_t = (t / 3) * PADW + (t % 3);
    const __nv_bfloat16* a0 = aBase + (size_t)off_t * CC + q * 64;
    const __nv_bfloat16* bs = bBase + t * CC + q * 64;
    #pragma unroll
    for (int i = 0; i < 4; i++) {       // A: 128 rows x 128B
        int slot = tid + 256 * i; int row = slot >> 3, c16 = slot & 7;
        cp16(sbase + SWZ(row * 128 + c16 * 16),
             (const char*)(a0 + (size_t)row * CC) + c16 * 16);
    }
    #pragma unroll
    for (int i = 0; i < 8; i++) {       // B: 256 couts x 128B
        int slot = tid + 256 * i; int row = slot >> 3, c16 = slot & 7;
        cp16(sbase + OFF_B + SWZ(row * 128 + c16 * 16),
             (const char*)(bs + (size_t)row * CIN_K) + c16 * 16);
    }
    asm volatile("cp.async.commit_group;" ::: "memory");
}

__global__ void __launch_bounds__(256)
conv_bf16_kernel(const float* __restrict__ bias, float* __restrict__ out) {
    extern __shared__ __align__(1024) char smem[];
    uint32_t sm = smem_u32(smem);
    int tid = threadIdx.x, wid = tid >> 5, lane = tid & 31;
    int b0 = blockIdx.x * 128;
    int n  = blockIdx.y;
    int wm = wid & 1, wn = wid >> 1;    // warp tile: 64 pixels x 64 couts

    float* s_bias  = (float*)(smem + OFF_AB);
    float* s_alpha = (float*)(smem + OFF_AB + 1024);
    s_bias[tid]  = bias[tid];
    s_alpha[tid] = g_alpha[tid];

    const __nv_bfloat16* aBase = g_xbf + ((size_t)n * XBP_PIX + b0) * CC;
    const __nv_bfloat16* bBase = g_wbf;

    int lrow = (lane & 7) + ((lane >> 3) & 1) * 8;
    uint32_t ltb = (uint32_t)((lane >> 4) * 16);
    uint32_t xk  = (uint32_t)((lane & 7) << 4);
    uint32_t aA[4], aB[4];
    #pragma unroll
    for (int mi = 0; mi < 4; mi++) aA[mi] = (uint32_t)((wm * 64 + mi * 16 + lrow) * 128);
    #pragma unroll
    for (int nj = 0; nj < 4; nj++) aB[nj] = (uint32_t)(OFF_B + (wn * 64 + nj * 16 + lrow) * 128);

    float acc[4][8][4];
    #pragma unroll
    for (int mi = 0; mi < 4; mi++)
        #pragma unroll
        for (int ni = 0; ni < 8; ni++)
            #pragma unroll
            for (int j = 0; j < 4; j++) acc[mi][ni][j] = 0.f;

    load_stage_bf(sm, aBase, bBase, 0, tid);

    for (int k = 0; k < NCH; k++) {
        asm volatile("cp.async.wait_group 0;" ::: "memory");
        __syncthreads();
        // slot (k+1)&1 was last read during compute of chunk k-1, which every
        // warp finished before this barrier -> safe to overwrite now.
        if (k + 1 < NCH)
            load_stage_bf(sm + ((k + 1) & 1) * STAGE, aBase, bBase, k + 1, tid);

        uint32_t sb = sm + (k & 1) * STAGE;
        #pragma unroll
        for (int ks = 0; ks < 4; ks++) {                 // 16-ch slices
            uint32_t off = (((uint32_t)(ks << 5)) | ltb) ^ xk;
            uint32_t a[4][4], bf[4][4];
            #pragma unroll
            for (int mi = 0; mi < 4; mi++) ldsm4(a[mi], sb + aA[mi] + off);
            #pragma unroll
            for (int nj = 0; nj < 4; nj++) ldsm4(bf[nj], sb + aB[nj] + off);
            #pragma unroll
            for (int mi = 0; mi < 4; mi++)
                #pragma unroll
                for (int ni = 0; ni < 8; ni++) {
                    int nj = ni >> 1, sel = ni & 1;
                    mma_bf16(acc[mi][ni], a[mi], bf[nj][sel], bf[nj][sel + 2]);
                }
        }
    }

    #pragma unroll
    for (int mi = 0; mi < 4; mi++)
        #pragma unroll
        for (int half = 0; half < 2; half++) {
            int b = b0 + wm * 64 + mi * 16 + (lane >> 2) + half * 8;
            int h = b / PADW, wp = b % PADW;
            bool valid = (h < HH) && (wp < WW);
            float bm = valid ? g_betamap[(size_t)n * HW + h * WW + wp] : 0.f;
            float* obase = out + (size_t)n * COUT * HW + h * WW + wp;
            if (valid) {
                #pragma unroll
                for (int ni = 0; ni < 8; ni++)
                    #pragma unroll
                    for (int j2 = 0; j2 < 2; j2++) {
                        int co = wn * 64 + ni * 8 + 2 * (lane & 3) + j2;
                        float v = (acc[mi][ni][half * 2 + j2] + s_bias[co])
                                  * bm * s_alpha[co];
                        obase[(size_t)co * HW] = fmaxf(v, 0.f);
                    }
            }
        }
}

// ---------------- launcher ----------------
extern "C" void kernel_launch(void* const* d_in, const int* in_sizes, int n_in,
                              void* d_out, int out_size) {
    const float* x       = (const float*)d_in[0];
    const float* gamma   = (const float*)d_in[1];
    const float* beta_bn = (const float*)d_in[2];
    const float* Wt      = (const float*)d_in[3];
    const float* b       = (const float*)d_in[4];
    float* out = (float*)d_out;

    cudaFuncSetAttribute(conv_bf16_kernel,
                         cudaFuncAttributeMaxDynamicSharedMemorySize, SMEM_TOT);

    stats_part_kernel<<<dim3(CC, 8), 256>>>(x);
    stats_final_kernel<<<1, 256>>>(gamma, beta_bn);
    binact_pack_kernel<<<(NHW + 255) / 256, 256>>>(x);
    boxwprep_kernel<<<BOX_BLOCKS + COUT, 256>>>(Wt);
    conv_bf16_kernel<<<dim3(27, NB), 256, SMEM_TOT>>>(b, out);
}